// round 2
// baseline (speedup 1.0000x reference)
#include <cuda_runtime.h>
#include <cuda_bf16.h>
#include <cstdint>

#define IN_DIM   4096
#define OUT_DIM  4096
#define TOKENS   4096
#define RANK     64
#define VDIM     8
#define NIDX     (IN_DIM / VDIM)   // 512 indices per row

// 64 MB scratch for the materialized weight matrix (static device global: allowed)
__device__ float g_W[(size_t)OUT_DIM * IN_DIM];

// ---------------------------------------------------------------------------
// Kernel 1: materialize W[o][j] =
//   centroids[indices[o][perm[j]/8]][perm[j]%8] * scale[o] + wbias[o]
//   + sum_r U[o][r]*S[r]*Vt[r][j]
// Tile: 32 rows x 128 cols per CTA, 256 threads.
// ---------------------------------------------------------------------------
__global__ __launch_bounds__(256) void dequant_kernel(
    const float* __restrict__ centroids,   // [8192, 8]
    const int*   __restrict__ indices,     // [4096, 512]
    const int*   __restrict__ perm,        // [4096]
    const float* __restrict__ wscale,      // [4096, 1]
    const float* __restrict__ wbias,       // [4096, 1]
    const float* __restrict__ U,           // [4096, 64]
    const float* __restrict__ S,           // [64]
    const float* __restrict__ Vt)          // [64, 4096]
{
    __shared__ float s_us[32 * RANK];      // U*S for the 32 rows     (8 KB)
    __shared__ float s_vt[RANK * 128];     // Vt tile [64][128]       (32 KB)
    __shared__ int   s_perm[128];

    const int o0 = blockIdx.y * 32;
    const int j0 = blockIdx.x * 128;
    const int tid = threadIdx.x;

    for (int i = tid; i < 32 * RANK; i += 256) {
        int o = i >> 6, r = i & (RANK - 1);
        s_us[i] = U[(size_t)(o0 + o) * RANK + r] * S[r];
    }
    for (int i = tid; i < RANK * 128; i += 256) {
        int r = i >> 7, j = i & 127;
        s_vt[i] = Vt[(size_t)r * IN_DIM + j0 + j];
    }
    if (tid < 128) s_perm[tid] = perm[j0 + tid];
    __syncthreads();

    #pragma unroll 4
    for (int i = 0; i < 16; i++) {
        int id = i * 256 + tid;            // 0..4095 over the 32x128 tile
        int ol = id >> 7;                  // local row
        int jl = id & 127;                 // local col (consecutive per warp -> coalesced)
        int o  = o0 + ol;
        int pj = s_perm[jl];
        int ci = indices[(size_t)o * NIDX + (pj >> 3)];
        float acc = centroids[(size_t)ci * VDIM + (pj & 7)] * wscale[o] + wbias[o];
        const float* us = &s_us[ol * RANK];
        #pragma unroll
        for (int r = 0; r < RANK; r++)
            acc += us[r] * s_vt[r * 128 + jl];
        g_W[(size_t)o * IN_DIM + j0 + jl] = acc;
    }
}

// ---------------------------------------------------------------------------
// Kernel 2: out[m][n] = sum_k x[m][k] * W[n][k] + bias[n]
// Both operands K-major (NT layout). 128x128 tile, BK=8, 8x8 per thread.
// Software-pipelined: next K-slab is prefetched into registers during compute.
// ---------------------------------------------------------------------------
#define BM 128
#define BN 128
#define BK 8

__global__ __launch_bounds__(256) void sgemm_kernel(
    const float* __restrict__ A,           // x [4096, 4096]
    const float* __restrict__ bias,        // [4096]
    float* __restrict__ C)                 // [4096, 4096]
{
    const float* B = g_W;

    __shared__ float As[BK][BM];
    __shared__ float Bs[BK][BN];

    const int tid = threadIdx.x;
    const int m0 = blockIdx.y * BM;
    const int n0 = blockIdx.x * BN;
    const int tr = tid / 16;               // 0..15
    const int tc = tid % 16;               // 0..15

    // global->shared load mapping: 128 rows x 8 k, one float4 per thread
    const int lr = tid >> 1;               // 0..127
    const int lc = (tid & 1) * 4;          // 0 or 4

    const float* aptr = &A[(size_t)(m0 + lr) * IN_DIM + lc];
    const float* bptr = &B[(size_t)(n0 + lr) * IN_DIM + lc];

    float acc[8][8] = {};

    // prologue: fetch first slab
    float4 a = *(const float4*)(aptr);
    float4 b = *(const float4*)(bptr);

    for (int k0 = 0; k0 < IN_DIM; k0 += BK) {
        As[lc + 0][lr] = a.x; As[lc + 1][lr] = a.y;
        As[lc + 2][lr] = a.z; As[lc + 3][lr] = a.w;
        Bs[lc + 0][lr] = b.x; Bs[lc + 1][lr] = b.y;
        Bs[lc + 2][lr] = b.z; Bs[lc + 3][lr] = b.w;
        __syncthreads();

        // prefetch next slab while computing this one
        if (k0 + BK < IN_DIM) {
            a = *(const float4*)(aptr + k0 + BK);
            b = *(const float4*)(bptr + k0 + BK);
        }

        #pragma unroll
        for (int kk = 0; kk < BK; kk++) {
            float ra[8], rb[8];
            #pragma unroll
            for (int i = 0; i < 8; i++) ra[i] = As[kk][tr * 8 + i];
            #pragma unroll
            for (int j = 0; j < 8; j++) rb[j] = Bs[kk][tc * 8 + j];
            #pragma unroll
            for (int i = 0; i < 8; i++)
                #pragma unroll
                for (int j = 0; j < 8; j++)
                    acc[i][j] += ra[i] * rb[j];
        }
        __syncthreads();
    }

    #pragma unroll
    for (int i = 0; i < 8; i++) {
        int m = m0 + tr * 8 + i;
        #pragma unroll
        for (int j = 0; j < 8; j += 4) {
            int n = n0 + tc * 8 + j;
            float4 v;
            v.x = acc[i][j + 0] + bias[n + 0];
            v.y = acc[i][j + 1] + bias[n + 1];
            v.z = acc[i][j + 2] + bias[n + 2];
            v.w = acc[i][j + 3] + bias[n + 3];
            *(float4*)&C[(size_t)m * OUT_DIM + n] = v;
        }
    }
}

// ---------------------------------------------------------------------------
extern "C" void kernel_launch(void* const* d_in, const int* in_sizes, int n_in,
                              void* d_out, int out_size)
{
    const float* x         = (const float*)d_in[0];
    const float* centroids = (const float*)d_in[1];
    const int*   indices   = (const int*)  d_in[2];
    const int*   perm      = (const int*)  d_in[3];
    const float* wscale    = (const float*)d_in[4];
    const float* wbias     = (const float*)d_in[5];
    const float* U         = (const float*)d_in[6];
    const float* S         = (const float*)d_in[7];
    const float* Vt        = (const float*)d_in[8];
    const float* bias      = (const float*)d_in[9];
    float* out = (float*)d_out;

    dequant_kernel<<<dim3(IN_DIM / 128, OUT_DIM / 32), 256>>>(
        centroids, indices, perm, wscale, wbias, U, S, Vt);

    sgemm_kernel<<<dim3(OUT_DIM / BN, TOKENS / BM), 256>>>(x, bias, out);
}

// round 4
// speedup vs baseline: 2.1415x; 2.1415x over previous
#include <cuda_runtime.h>
#include <cuda_bf16.h>
#include <cstdint>

#define IN_DIM   4096
#define OUT_DIM  4096
#define TOKENS   4096
#define RANK     64
#define VDIM     8
#define NIDX     (IN_DIM / VDIM)

// ---------------------------------------------------------------------------
// Device-global scratch (allocation-free): split bf16 operands
// ---------------------------------------------------------------------------
__device__ __nv_bfloat16 g_Whi[(size_t)OUT_DIM * IN_DIM];
__device__ __nv_bfloat16 g_Wlo[(size_t)OUT_DIM * IN_DIM];
__device__ __nv_bfloat16 g_xhi[(size_t)TOKENS * IN_DIM];
__device__ __nv_bfloat16 g_xlo[(size_t)TOKENS * IN_DIM];

// ---------------------------------------------------------------------------
// PTX helpers (baseline compute_100-legal: cp.async, ldmatrix, mma.sync)
// ---------------------------------------------------------------------------
static __device__ __forceinline__ uint32_t smem_u32(const void* p) {
    uint32_t a;
    asm("{ .reg .u64 t; cvta.to.shared.u64 t, %1; cvt.u32.u64 %0, t; }" : "=r"(a) : "l"(p));
    return a;
}

#define CP_ASYNC16(dst, src) \
    asm volatile("cp.async.cg.shared.global [%0], [%1], 16;\n" :: "r"(dst), "l"(src))
#define CP_COMMIT() asm volatile("cp.async.commit_group;\n" ::: "memory")
#define CP_WAIT1()  asm volatile("cp.async.wait_group 1;\n" ::: "memory")
#define CP_WAIT0()  asm volatile("cp.async.wait_group 0;\n" ::: "memory")

#define LDSM_X4(r0, r1, r2, r3, addr) \
    asm volatile("ldmatrix.sync.aligned.m8n8.x4.shared.b16 {%0,%1,%2,%3}, [%4];" \
        : "=r"(r0), "=r"(r1), "=r"(r2), "=r"(r3) : "r"(addr))

#define MMA16816(c, a, b) \
    asm volatile("mma.sync.aligned.m16n8k16.row.col.f32.bf16.bf16.f32 " \
        "{%0,%1,%2,%3}, {%4,%5,%6,%7}, {%8,%9}, {%0,%1,%2,%3};" \
        : "+f"((c)[0]), "+f"((c)[1]), "+f"((c)[2]), "+f"((c)[3]) \
        : "r"((a)[0]), "r"((a)[1]), "r"((a)[2]), "r"((a)[3]), \
          "r"((b)[0]), "r"((b)[1]))

// ---------------------------------------------------------------------------
// Kernel 1: dequant -> split bf16 weights
// ---------------------------------------------------------------------------
__global__ __launch_bounds__(256) void dequant_kernel(
    const float* __restrict__ centroids, const int* __restrict__ indices,
    const int* __restrict__ perm, const float* __restrict__ wscale,
    const float* __restrict__ wbias, const float* __restrict__ U,
    const float* __restrict__ S, const float* __restrict__ Vt)
{
    __shared__ float s_us[32 * RANK];
    __shared__ float s_vt[RANK * 128];
    __shared__ int   s_perm[128];

    const int o0 = blockIdx.y * 32;
    const int j0 = blockIdx.x * 128;
    const int tid = threadIdx.x;

    for (int i = tid; i < 32 * RANK; i += 256) {
        int o = i >> 6, r = i & (RANK - 1);
        s_us[i] = U[(size_t)(o0 + o) * RANK + r] * S[r];
    }
    for (int i = tid; i < RANK * 128; i += 256) {
        int r = i >> 7, j = i & 127;
        s_vt[i] = Vt[(size_t)r * IN_DIM + j0 + j];
    }
    if (tid < 128) s_perm[tid] = perm[j0 + tid];
    __syncthreads();

    #pragma unroll 4
    for (int i = 0; i < 16; i++) {
        int id = i * 256 + tid;
        int ol = id >> 7;
        int jl = id & 127;
        int o  = o0 + ol;
        int pj = s_perm[jl];
        int ci = indices[(size_t)o * NIDX + (pj >> 3)];
        float acc = centroids[(size_t)ci * VDIM + (pj & 7)] * wscale[o] + wbias[o];
        const float* us = &s_us[ol * RANK];
        #pragma unroll
        for (int r = 0; r < RANK; r++)
            acc += us[r] * s_vt[r * 128 + jl];
        size_t idx = (size_t)o * IN_DIM + j0 + jl;
        __nv_bfloat16 hi = __float2bfloat16(acc);
        g_Whi[idx] = hi;
        g_Wlo[idx] = __float2bfloat16(acc - __bfloat162float(hi));
    }
}

// ---------------------------------------------------------------------------
// Kernel 2: split x into hi/lo bf16
// ---------------------------------------------------------------------------
__global__ __launch_bounds__(256) void convert_x_kernel(const float* __restrict__ x)
{
    size_t i = ((size_t)blockIdx.x * 256 + threadIdx.x) * 4;
    float4 v = *(const float4*)(x + i);
    __nv_bfloat16 h0 = __float2bfloat16(v.x);
    __nv_bfloat16 h1 = __float2bfloat16(v.y);
    __nv_bfloat16 h2 = __float2bfloat16(v.z);
    __nv_bfloat16 h3 = __float2bfloat16(v.w);
    __nv_bfloat162* ph = (__nv_bfloat162*)(g_xhi + i);
    ph[0] = __nv_bfloat162(h0, h1);
    ph[1] = __nv_bfloat162(h2, h3);
    __nv_bfloat162* pl = (__nv_bfloat162*)(g_xlo + i);
    pl[0] = __nv_bfloat162(__float2bfloat16(v.x - __bfloat162float(h0)),
                           __float2bfloat16(v.y - __bfloat162float(h1)));
    pl[1] = __nv_bfloat162(__float2bfloat16(v.z - __bfloat162float(h2)),
                           __float2bfloat16(v.w - __bfloat162float(h3)));
}

// ---------------------------------------------------------------------------
// Kernel 3: HMMA GEMM via mma.sync m16n8k16 bf16, 3-pass split.
//   C[m][n] = sum_k x[m][k]*W[n][k] + bias[n]
//   CTA 128x128, BK=32, 8 warps (warp tile 64x32), 2-stage cp.async pipeline.
// ---------------------------------------------------------------------------
#define BM 128
#define BN 128
#define BK 32
#define GKP 40            // padded k-stride (elements) -> conflict-free LDSM
#define NCHUNK (IN_DIM / BK)

#define TILE_BYTES (BM * GKP * 2)          // 10240
#define T_AHI 0
#define T_ALO (1 * TILE_BYTES)
#define T_BHI (2 * TILE_BYTES)
#define T_BLO (3 * TILE_BYTES)
#define STAGE_SZ (4 * TILE_BYTES)          // 40960
#define SMEM_TOTAL (2 * STAGE_SZ)          // 81920

static __device__ __forceinline__ void load_chunk(uint32_t stage, int m0, int n0,
                                                  int k0, int tid)
{
    #pragma unroll
    for (int t = 0; t < 2; t++) {
        int idx = t * 256 + tid;
        int row = idx >> 2;                 // 0..127
        int c   = idx & 3;                  // 16B chunk within 64B row
        uint32_t off = (uint32_t)(row * GKP + c * 8) * 2;
        size_t ga = (size_t)(m0 + row) * IN_DIM + k0 + c * 8;
        size_t gb = (size_t)(n0 + row) * IN_DIM + k0 + c * 8;
        CP_ASYNC16(stage + T_AHI + off, (const char*)(g_xhi + ga));
        CP_ASYNC16(stage + T_ALO + off, (const char*)(g_xlo + ga));
        CP_ASYNC16(stage + T_BHI + off, (const char*)(g_Whi + gb));
        CP_ASYNC16(stage + T_BLO + off, (const char*)(g_Wlo + gb));
    }
    CP_COMMIT();
}

__global__ __launch_bounds__(256, 1) void gemm_kernel(
    const float* __restrict__ bias, float* __restrict__ C)
{
    extern __shared__ char smem[];
    const uint32_t sb = smem_u32(smem);
    const int tid  = threadIdx.x;
    const int wid  = tid >> 5;
    const int lane = tid & 31;
    const int wm   = wid >> 2;              // 0..1 : warp row (64 m each)
    const int wn   = wid & 3;               // 0..3 : warp col (32 n each)
    const int m0   = blockIdx.y * BM;
    const int n0   = blockIdx.x * BN;

    // per-lane ldmatrix byte offsets (within a tile)
    // A (m16k16 via x4): row = warp_m + mi*16 + (lane&15), colblk = (lane>>4)*8 elems
    const uint32_t a_off =
        (uint32_t)(((wm * 64 + (lane & 15)) * GKP + ((lane >> 4) & 1) * 8) * 2);
    // B (two n8k16 tiles via x4): row = warp_n + g*16 + ((lane>>4)&1)*8 + (lane&7),
    //                             kblk = ((lane>>3)&1)*8 elems
    const uint32_t b_off =
        (uint32_t)(((wn * 32 + ((lane >> 4) & 1) * 8 + (lane & 7)) * GKP +
                    ((lane >> 3) & 1) * 8) * 2);

    float acc[4][4][4];
    #pragma unroll
    for (int i = 0; i < 4; i++)
        #pragma unroll
        for (int j = 0; j < 4; j++)
            #pragma unroll
            for (int k = 0; k < 4; k++) acc[i][j][k] = 0.f;

    // prologue: chunks 0 and 1
    load_chunk(sb,            m0, n0, 0,  tid);
    load_chunk(sb + STAGE_SZ, m0, n0, BK, tid);

    for (int i = 0; i < NCHUNK; i++) {
        const uint32_t stage = sb + (i & 1) * STAGE_SZ;
        if (i == NCHUNK - 1) { CP_WAIT0(); } else { CP_WAIT1(); }
        __syncthreads();

        #pragma unroll
        for (int ks = 0; ks < 2; ks++) {
            const uint32_t kb = ks * 32;    // 16 elems * 2B
            uint32_t ahi[4][4], alo[4][4], bhi[4][2], blo[4][2];
            #pragma unroll
            for (int mi = 0; mi < 4; mi++) {
                uint32_t ad = stage + a_off + mi * (16 * GKP * 2) + kb;
                LDSM_X4(ahi[mi][0], ahi[mi][1], ahi[mi][2], ahi[mi][3], ad + T_AHI);
                LDSM_X4(alo[mi][0], alo[mi][1], alo[mi][2], alo[mi][3], ad + T_ALO);
            }
            #pragma unroll
            for (int g = 0; g < 2; g++) {
                uint32_t bd = stage + b_off + g * (16 * GKP * 2) + kb;
                LDSM_X4(bhi[2*g][0], bhi[2*g][1], bhi[2*g+1][0], bhi[2*g+1][1], bd + T_BHI);
                LDSM_X4(blo[2*g][0], blo[2*g][1], blo[2*g+1][0], blo[2*g+1][1], bd + T_BLO);
            }
            #pragma unroll
            for (int mi = 0; mi < 4; mi++)
                #pragma unroll
                for (int nj = 0; nj < 4; nj++) {
                    MMA16816(acc[mi][nj], ahi[mi], bhi[nj]);
                    MMA16816(acc[mi][nj], ahi[mi], blo[nj]);
                    MMA16816(acc[mi][nj], alo[mi], bhi[nj]);
                }
        }

        __syncthreads();
        if (i + 2 < NCHUNK)
            load_chunk(stage, m0, n0, (i + 2) * BK, tid);
    }

    // epilogue: acc[mi][nj]: c0=(r,c) c1=(r,c+1) c2=(r+8,c) c3=(r+8,c+1)
    #pragma unroll
    for (int mi = 0; mi < 4; mi++) {
        int r = m0 + wm * 64 + mi * 16 + (lane >> 2);
        #pragma unroll
        for (int nj = 0; nj < 4; nj++) {
            int c = n0 + wn * 32 + nj * 8 + (lane & 3) * 2;
            float2 bv = *(const float2*)(bias + c);
            float2 v0 = { acc[mi][nj][0] + bv.x, acc[mi][nj][1] + bv.y };
            float2 v1 = { acc[mi][nj][2] + bv.x, acc[mi][nj][3] + bv.y };
            *(float2*)(C + (size_t)r * OUT_DIM + c)       = v0;
            *(float2*)(C + (size_t)(r + 8) * OUT_DIM + c) = v1;
        }
    }
}

// ---------------------------------------------------------------------------
extern "C" void kernel_launch(void* const* d_in, const int* in_sizes, int n_in,
                              void* d_out, int out_size)
{
    const float* x         = (const float*)d_in[0];
    const float* centroids = (const float*)d_in[1];
    const int*   indices   = (const int*)  d_in[2];
    const int*   perm      = (const int*)  d_in[3];
    const float* wscale    = (const float*)d_in[4];
    const float* wbias     = (const float*)d_in[5];
    const float* U         = (const float*)d_in[6];
    const float* S         = (const float*)d_in[7];
    const float* Vt        = (const float*)d_in[8];
    const float* bias      = (const float*)d_in[9];
    float* out = (float*)d_out;

    dequant_kernel<<<dim3(IN_DIM / 128, OUT_DIM / 32), 256>>>(
        centroids, indices, perm, wscale, wbias, U, S, Vt);

    convert_x_kernel<<<(TOKENS * (IN_DIM / 4)) / 256, 256>>>(x);

    cudaFuncSetAttribute(gemm_kernel, cudaFuncAttributeMaxDynamicSharedMemorySize,
                         SMEM_TOTAL);
    gemm_kernel<<<dim3(OUT_DIM / BN, TOKENS / BM), 256, SMEM_TOTAL>>>(bias, out);
}

// round 6
// speedup vs baseline: 3.6357x; 1.6978x over previous
#include <cuda_runtime.h>
#include <cuda_fp16.h>
#include <cstdint>

#define IN_DIM   4096
#define OUT_DIM  4096
#define TOKENS   4096
#define RANK     64
#define VDIM     8
#define NIDX     (IN_DIM / VDIM)

// ---------------------------------------------------------------------------
// Device-global scratch: fp16 operands. W split into hi + 32*lo.
// ---------------------------------------------------------------------------
__device__ __half g_Whi[(size_t)OUT_DIM * IN_DIM];
__device__ __half g_Wlos[(size_t)OUT_DIM * IN_DIM];   // (W - Whi) * 32
__device__ __half g_xhi[(size_t)TOKENS * IN_DIM];

// ---------------------------------------------------------------------------
// PTX helpers (baseline compute_100-legal)
// ---------------------------------------------------------------------------
static __device__ __forceinline__ uint32_t smem_u32(const void* p) {
    uint32_t a;
    asm("{ .reg .u64 t; cvta.to.shared.u64 t, %1; cvt.u32.u64 %0, t; }" : "=r"(a) : "l"(p));
    return a;
}

#define CP_ASYNC16(dst, src) \
    asm volatile("cp.async.cg.shared.global [%0], [%1], 16;\n" :: "r"(dst), "l"(src))
#define CP_COMMIT() asm volatile("cp.async.commit_group;\n" ::: "memory")
#define CP_WAIT1()  asm volatile("cp.async.wait_group 1;\n" ::: "memory")
#define CP_WAIT0()  asm volatile("cp.async.wait_group 0;\n" ::: "memory")

#define LDSM_X4(r0, r1, r2, r3, addr) \
    asm volatile("ldmatrix.sync.aligned.m8n8.x4.shared.b16 {%0,%1,%2,%3}, [%4];" \
        : "=r"(r0), "=r"(r1), "=r"(r2), "=r"(r3) : "r"(addr))

#define MMA16816F(c, a, b) \
    asm volatile("mma.sync.aligned.m16n8k16.row.col.f32.f16.f16.f32 " \
        "{%0,%1,%2,%3}, {%4,%5,%6,%7}, {%8,%9}, {%0,%1,%2,%3};" \
        : "+f"((c)[0]), "+f"((c)[1]), "+f"((c)[2]), "+f"((c)[3]) \
        : "r"((a)[0]), "r"((a)[1]), "r"((a)[2]), "r"((a)[3]), \
          "r"((b)[0]), "r"((b)[1]))

#define HMUL2(d, a, s) \
    asm("mul.f16x2 %0, %1, %2;" : "=r"(d) : "r"(a), "r"(s))

// half2(1/32, 1/32) — exponent-only scale, exact
#define SC_1_32 0x28002800u

// ---------------------------------------------------------------------------
// Kernel 1: dequant -> Whi (fp16), Wlos = (W - Whi)*32 (fp16)
//   Tile 32 rows x 128 cols, 256 threads; thread computes a 4x4 block.
// ---------------------------------------------------------------------------
__global__ __launch_bounds__(256) void dequant_kernel(
    const float* __restrict__ centroids, const int* __restrict__ indices,
    const int* __restrict__ perm, const float* __restrict__ wscale,
    const float* __restrict__ wbias, const float* __restrict__ U,
    const float* __restrict__ S, const float* __restrict__ Vt)
{
    __shared__ float s_us[32 * RANK];      // [ol][r], 8 KB
    __shared__ float s_vt[RANK * 128];     // [r][j],  32 KB
    __shared__ int   s_perm[128];

    const int o0 = blockIdx.y * 32;
    const int j0 = blockIdx.x * 128;
    const int tid = threadIdx.x;
    const int tr = tid >> 5;               // 0..7  -> rows tr*4 .. tr*4+3
    const int tc = tid & 31;               // 0..31 -> cols tc*4 .. tc*4+3

    for (int i = tid; i < 32 * RANK; i += 256) {
        int o = i >> 6, r = i & (RANK - 1);
        s_us[i] = U[(size_t)(o0 + o) * RANK + r] * S[r];
    }
    for (int i = tid; i < RANK * 128; i += 256) {
        int r = i >> 7, j = i & 127;
        s_vt[i] = Vt[(size_t)r * IN_DIM + j0 + j];
    }
    if (tid < 128) s_perm[tid] = perm[j0 + tid];
    __syncthreads();

    // ---- gather phase: 16 indices then 16 centroids (high MLP) ----
    int pj[4];
    #pragma unroll
    for (int jj = 0; jj < 4; jj++) pj[jj] = s_perm[tc * 4 + jj];

    int ci[4][4];
    #pragma unroll
    for (int i = 0; i < 4; i++) {
        int o = o0 + tr * 4 + i;
        #pragma unroll
        for (int jj = 0; jj < 4; jj++)
            ci[i][jj] = indices[(size_t)o * NIDX + (pj[jj] >> 3)];
    }
    float cv[4][4];
    #pragma unroll
    for (int i = 0; i < 4; i++)
        #pragma unroll
        for (int jj = 0; jj < 4; jj++)
            cv[i][jj] = centroids[(size_t)ci[i][jj] * VDIM + (pj[jj] & 7)];

    float acc[4][4];
    #pragma unroll
    for (int i = 0; i < 4; i++) {
        int o = o0 + tr * 4 + i;
        float sc = wscale[o], bi = wbias[o];
        #pragma unroll
        for (int jj = 0; jj < 4; jj++)
            acc[i][jj] = cv[i][jj] * sc + bi;
    }

    // ---- low-rank phase: 4x4 register block GEMM ----
    #pragma unroll
    for (int rb = 0; rb < RANK; rb += 4) {
        float4 us4[4];
        #pragma unroll
        for (int i = 0; i < 4; i++)
            us4[i] = *(const float4*)&s_us[(tr * 4 + i) * RANK + rb];
        #pragma unroll
        for (int rr = 0; rr < 4; rr++) {
            float4 v = *(const float4*)&s_vt[(rb + rr) * 128 + tc * 4];
            #pragma unroll
            for (int i = 0; i < 4; i++) {
                float u = (&us4[i].x)[rr];
                acc[i][0] += u * v.x;
                acc[i][1] += u * v.y;
                acc[i][2] += u * v.z;
                acc[i][3] += u * v.w;
            }
        }
    }

    // ---- split + store ----
    #pragma unroll
    for (int i = 0; i < 4; i++) {
        size_t idx = (size_t)(o0 + tr * 4 + i) * IN_DIM + j0 + tc * 4;
        __half h[4], l[4];
        #pragma unroll
        for (int jj = 0; jj < 4; jj++) {
            h[jj] = __float2half_rn(acc[i][jj]);
            l[jj] = __float2half_rn((acc[i][jj] - __half2float(h[jj])) * 32.0f);
        }
        *(__half2*)(g_Whi  + idx)     = __halves2half2(h[0], h[1]);
        *(__half2*)(g_Whi  + idx + 2) = __halves2half2(h[2], h[3]);
        *(__half2*)(g_Wlos + idx)     = __halves2half2(l[0], l[1]);
        *(__half2*)(g_Wlos + idx + 2) = __halves2half2(l[2], l[3]);
    }
}

// ---------------------------------------------------------------------------
// Kernel 2: x -> fp16
// ---------------------------------------------------------------------------
__global__ __launch_bounds__(256) void convert_x_kernel(const float* __restrict__ x)
{
    size_t i = ((size_t)blockIdx.x * 256 + threadIdx.x) * 4;
    float4 v = *(const float4*)(x + i);
    *(__half2*)(g_xhi + i)     = __floats2half2_rn(v.x, v.y);
    *(__half2*)(g_xhi + i + 2) = __floats2half2_rn(v.z, v.w);
}

// ---------------------------------------------------------------------------
// Kernel 3: HMMA GEMM, 2-pass fp16 split:
//   C = xhi*Whi + (xhi/32)*Wlos + bias   (fp32 accumulate)
//   CTA 128x128, BK=32, 8 warps (warp tile 64x32), 2-stage cp.async pipeline.
// ---------------------------------------------------------------------------
#define BM 128
#define BN 128
#define BK 32
#define GKP 40
#define NCHUNK (IN_DIM / BK)

#define TILE_BYTES (BM * GKP * 2)          // 10240
#define T_AHI 0
#define T_BHI (1 * TILE_BYTES)
#define T_BLO (2 * TILE_BYTES)
#define STAGE_SZ (3 * TILE_BYTES)          // 30720
#define SMEM_TOTAL (2 * STAGE_SZ)          // 61440

static __device__ __forceinline__ void load_chunk(uint32_t stage, int m0, int n0,
                                                  int k0, int tid)
{
    #pragma unroll
    for (int t = 0; t < 2; t++) {
        int idx = t * 256 + tid;
        int row = idx >> 2;                 // 0..127
        int c   = idx & 3;                  // 16B chunk within 64B row
        uint32_t off = (uint32_t)(row * GKP + c * 8) * 2;
        size_t ga = (size_t)(m0 + row) * IN_DIM + k0 + c * 8;
        size_t gb = (size_t)(n0 + row) * IN_DIM + k0 + c * 8;
        CP_ASYNC16(stage + T_AHI + off, (const char*)(g_xhi  + ga));
        CP_ASYNC16(stage + T_BHI + off, (const char*)(g_Whi  + gb));
        CP_ASYNC16(stage + T_BLO + off, (const char*)(g_Wlos + gb));
    }
    CP_COMMIT();
}

__global__ __launch_bounds__(256, 1) void gemm_kernel(
    const float* __restrict__ bias, float* __restrict__ C)
{
    extern __shared__ char smem[];
    const uint32_t sb = smem_u32(smem);
    const int tid  = threadIdx.x;
    const int wid  = tid >> 5;
    const int lane = tid & 31;
    const int wm   = wid >> 2;              // 0..1 : warp row (64 m each)
    const int wn   = wid & 3;               // 0..3 : warp col (32 n each)
    const int m0   = blockIdx.y * BM;
    const int n0   = blockIdx.x * BN;

    const uint32_t a_off =
        (uint32_t)(((wm * 64 + (lane & 15)) * GKP + ((lane >> 4) & 1) * 8) * 2);
    const uint32_t b_off =
        (uint32_t)(((wn * 32 + ((lane >> 4) & 1) * 8 + (lane & 7)) * GKP +
                    ((lane >> 3) & 1) * 8) * 2);

    float acc[4][4][4];
    #pragma unroll
    for (int i = 0; i < 4; i++)
        #pragma unroll
        for (int j = 0; j < 4; j++)
            #pragma unroll
            for (int k = 0; k < 4; k++) acc[i][j][k] = 0.f;

    load_chunk(sb,            m0, n0, 0,  tid);
    load_chunk(sb + STAGE_SZ, m0, n0, BK, tid);

    for (int i = 0; i < NCHUNK; i++) {
        const uint32_t stage = sb + (i & 1) * STAGE_SZ;
        if (i == NCHUNK - 1) { CP_WAIT0(); } else { CP_WAIT1(); }
        __syncthreads();

        #pragma unroll
        for (int ks = 0; ks < 2; ks++) {
            const uint32_t kb = ks * 32;    // 16 elems * 2B
            uint32_t ahi[4][4], ahs[4][4], bhi[4][2], blo[4][2];
            #pragma unroll
            for (int mi = 0; mi < 4; mi++) {
                uint32_t ad = stage + a_off + mi * (16 * GKP * 2) + kb;
                LDSM_X4(ahi[mi][0], ahi[mi][1], ahi[mi][2], ahi[mi][3], ad + T_AHI);
                #pragma unroll
                for (int q = 0; q < 4; q++)
                    HMUL2(ahs[mi][q], ahi[mi][q], SC_1_32);
            }
            #pragma unroll
            for (int g = 0; g < 2; g++) {
                uint32_t bd = stage + b_off + g * (16 * GKP * 2) + kb;
                LDSM_X4(bhi[2*g][0], bhi[2*g][1], bhi[2*g+1][0], bhi[2*g+1][1], bd + T_BHI);
                LDSM_X4(blo[2*g][0], blo[2*g][1], blo[2*g+1][0], blo[2*g+1][1], bd + T_BLO);
            }
            #pragma unroll
            for (int mi = 0; mi < 4; mi++)
                #pragma unroll
                for (int nj = 0; nj < 4; nj++) {
                    MMA16816F(acc[mi][nj], ahi[mi], bhi[nj]);
                    MMA16816F(acc[mi][nj], ahs[mi], blo[nj]);
                }
        }

        __syncthreads();
        if (i + 2 < NCHUNK)
            load_chunk(stage, m0, n0, (i + 2) * BK, tid);
    }

    #pragma unroll
    for (int mi = 0; mi < 4; mi++) {
        int r = m0 + wm * 64 + mi * 16 + (lane >> 2);
        #pragma unroll
        for (int nj = 0; nj < 4; nj++) {
            int c = n0 + wn * 32 + nj * 8 + (lane & 3) * 2;
            float2 bv = *(const float2*)(bias + c);
            float2 v0 = { acc[mi][nj][0] + bv.x, acc[mi][nj][1] + bv.y };
            float2 v1 = { acc[mi][nj][2] + bv.x, acc[mi][nj][3] + bv.y };
            *(float2*)(C + (size_t)r * OUT_DIM + c)       = v0;
            *(float2*)(C + (size_t)(r + 8) * OUT_DIM + c) = v1;
        }
    }
}

// ---------------------------------------------------------------------------
extern "C" void kernel_launch(void* const* d_in, const int* in_sizes, int n_in,
                              void* d_out, int out_size)
{
    const float* x         = (const float*)d_in[0];
    const float* centroids = (const float*)d_in[1];
    const int*   indices   = (const int*)  d_in[2];
    const int*   perm      = (const int*)  d_in[3];
    const float* wscale    = (const float*)d_in[4];
    const float* wbias     = (const float*)d_in[5];
    const float* U         = (const float*)d_in[6];
    const float* S         = (const float*)d_in[7];
    const float* Vt        = (const float*)d_in[8];
    const float* bias      = (const float*)d_in[9];
    float* out = (float*)d_out;

    dequant_kernel<<<dim3(IN_DIM / 128, OUT_DIM / 32), 256>>>(
        centroids, indices, perm, wscale, wbias, U, S, Vt);

    convert_x_kernel<<<(TOKENS * (IN_DIM / 4)) / 256, 256>>>(x);

    cudaFuncSetAttribute(gemm_kernel, cudaFuncAttributeMaxDynamicSharedMemorySize,
                         SMEM_TOTAL);
    gemm_kernel<<<dim3(OUT_DIM / BN, TOKENS / BM), 256, SMEM_TOTAL>>>(bias, out);
}